// round 15
// baseline (speedup 1.0000x reference)
#include <cuda_runtime.h>

// ============================================================================
// SpikingCNN: conv1d -> BN(train) -> LIF -> maxpool2, three blocks.
// B=32. L1: 2->16 K5 s4 p2 T65536->16384->8192
//       L2: 16->32 K5 s1 p2 T8192->8192->4096
//       L3: 32->64 K3 s1 p1 T4096->4096->2048
// R12 finding: rel_err bit-identical across chunkings => error is a
// deterministic numerical mismatch (amplified ulp flips), NOT seams.
// R12 change: inv = rsqrtf(var_f32 + eps_f32)  (libdevice __nv_rsqrtf,
// matching XLA:GPU's lowering of jax.lax.rsqrt) instead of fp64 1/sqrt.
// ============================================================================

// Scratch (device globals; no allocation allowed)
__device__ float  g_bufA[8388608];   // conv outputs (all three layers are 8.39M)
__device__ float  g_bufS[4194304];   // spike outputs of L1 then L2
__device__ double g_psum[64 * 32];
__device__ double g_psq [64 * 32];
__device__ float  g_mean[64];
__device__ float  g_inv [64];

static __device__ __forceinline__ float4 ld4g(const float* __restrict__ p, int idx, int n) {
    // idx is always a multiple of 4 and n a multiple of 4 -> whole float4 in or out
    if (idx >= 0 && idx < n) return *reinterpret_cast<const float4*>(p + idx);
    return make_float4(0.f, 0.f, 0.f, 0.f);
}

// ---------------------------------------------------------------------------
// conv1: x(32,2,65536) -> g_bufA(32,16,16384), K=5, stride=4, pad=2
// ---------------------------------------------------------------------------
__global__ __launch_bounds__(128) void conv1_kernel(const float* __restrict__ x,
                                                    const float* __restrict__ w,
                                                    const float* __restrict__ bias) {
    const int g  = blockIdx.x * blockDim.x + threadIdx.x;  // 0..2047 (16384/8)
    const int co = blockIdx.y;                             // 0..15
    const int b  = blockIdx.z;                             // 0..31

    float wv[2][5];
#pragma unroll
    for (int ci = 0; ci < 2; ci++)
#pragma unroll
        for (int k = 0; k < 5; k++)
            wv[ci][k] = __ldg(w + (co * 2 + ci) * 5 + k);

    float acc[8];
    const float bb = __ldg(bias + co);
#pragma unroll
    for (int j = 0; j < 8; j++) acc[j] = bb;

    const int base = 32 * g - 4;
#pragma unroll
    for (int ci = 0; ci < 2; ci++) {
        const float* row = x + (b * 2 + ci) * 65536;
        float win[36];
#pragma unroll
        for (int q = 0; q < 9; q++) {
            float4 v = ld4g(row, base + 4 * q, 65536);
            win[4 * q + 0] = v.x; win[4 * q + 1] = v.y;
            win[4 * q + 2] = v.z; win[4 * q + 3] = v.w;
        }
#pragma unroll
        for (int k = 0; k < 5; k++)
#pragma unroll
            for (int j = 0; j < 8; j++)
                acc[j] = fmaf(wv[ci][k], win[4 * j + k + 2], acc[j]);  // idx = 4t+k-2
    }

    float* out = g_bufA + (b * 16 + co) * 16384 + 8 * g;
    *reinterpret_cast<float4*>(out)     = make_float4(acc[0], acc[1], acc[2], acc[3]);
    *reinterpret_cast<float4*>(out + 4) = make_float4(acc[4], acc[5], acc[6], acc[7]);
}

// ---------------------------------------------------------------------------
// convN (layers 2,3): reads spikes from g_bufS, writes g_bufA.
// Thread computes 4 couts x 8 t (register blocked), weights staged in smem.
// ---------------------------------------------------------------------------
template <int CIN, int COUT, int K, int T, int PAD>
__global__ __launch_bounds__(128) void convN_kernel(const float* __restrict__ w,
                                                    const float* __restrict__ bias) {
    __shared__ __align__(16) float ws[CIN * K * 4];
    const int tid = threadIdx.x;
    const int co4 = blockIdx.y;  // group of 4 output channels
    const int b   = blockIdx.z;

    for (int i = tid; i < CIN * K * 4; i += blockDim.x) {
        const int ci = i / (K * 4);
        const int r  = i % (K * 4);
        const int k  = r / 4;
        const int c  = r % 4;
        ws[i] = w[((co4 * 4 + c) * CIN + ci) * K + k];
    }
    __syncthreads();

    const int g    = blockIdx.x * blockDim.x + tid;  // 0..T/8-1
    const int base = 8 * g - 4;

    float acc[4][8];
#pragma unroll
    for (int c = 0; c < 4; c++) {
        const float bb = __ldg(bias + co4 * 4 + c);
#pragma unroll
        for (int j = 0; j < 8; j++) acc[c][j] = bb;
    }

    for (int ci = 0; ci < CIN; ci++) {
        const float* row = g_bufS + (b * CIN + ci) * T;
        float win[16];
#pragma unroll
        for (int q = 0; q < 4; q++) {
            float4 v = ld4g(row, base + 4 * q, T);
            win[4 * q + 0] = v.x; win[4 * q + 1] = v.y;
            win[4 * q + 2] = v.z; win[4 * q + 3] = v.w;
        }
#pragma unroll
        for (int k = 0; k < K; k++) {
            const float4 wv = *reinterpret_cast<const float4*>(&ws[(ci * K + k) * 4]);
#pragma unroll
            for (int j = 0; j < 8; j++) {
                const float xv = win[j + k + (4 - PAD)];  // idx = t + k - PAD
                acc[0][j] = fmaf(wv.x, xv, acc[0][j]);
                acc[1][j] = fmaf(wv.y, xv, acc[1][j]);
                acc[2][j] = fmaf(wv.z, xv, acc[2][j]);
                acc[3][j] = fmaf(wv.w, xv, acc[3][j]);
            }
        }
    }

#pragma unroll
    for (int c = 0; c < 4; c++) {
        float* out = g_bufA + (b * COUT + co4 * 4 + c) * T + 8 * g;
        *reinterpret_cast<float4*>(out)     = make_float4(acc[c][0], acc[c][1], acc[c][2], acc[c][3]);
        *reinterpret_cast<float4*>(out + 4) = make_float4(acc[c][4], acc[c][5], acc[c][6], acc[c][7]);
    }
}

// ---------------------------------------------------------------------------
// BN stats: single pass, fp64 sum + sum-of-squares. Block = one (c, b) row.
// fp64 accumulation = center of any fp32 reduction tree's error distribution.
// ---------------------------------------------------------------------------
template <int C, int T>
__global__ void stats_kernel() {
    const int c = blockIdx.x, b = blockIdx.y;
    const float* row = g_bufA + (b * C + c) * T;
    double s = 0.0, q = 0.0;
    for (int t = threadIdx.x; t < T; t += 256) {
        const double v = (double)row[t];
        s += v;
        q += v * v;
    }
    __shared__ double shs[256];
    __shared__ double shq[256];
    shs[threadIdx.x] = s;
    shq[threadIdx.x] = q;
    __syncthreads();
    for (int o = 128; o > 0; o >>= 1) {
        if (threadIdx.x < o) {
            shs[threadIdx.x] += shs[threadIdx.x + o];
            shq[threadIdx.x] += shq[threadIdx.x + o];
        }
        __syncthreads();
    }
    if (threadIdx.x == 0) {
        g_psum[c * 32 + b] = shs[0];
        g_psq [c * 32 + b] = shq[0];
    }
}

template <int C, int T>
__global__ void stats_fin_kernel() {
    const int c = threadIdx.x;
    if (c >= C) return;
    double s = 0.0, q = 0.0;
    for (int i = 0; i < 32; i++) { s += g_psum[c * 32 + i]; q += g_psq[c * 32 + i]; }
    const double N    = (double)(32 * (long long)T);
    const double mean = s / N;
    const double var  = q / N - mean * mean;
    g_mean[c] = (float)mean;
    // Match reference: var is an fp32 tensor; eps added in fp32; lax.rsqrt
    // lowers to libdevice __nv_rsqrtf (~2-ulp approx) on XLA:GPU.
    const float var_f = (float)var;
    g_inv[c]  = rsqrtf(var_f + 1e-5f);
}

// ---------------------------------------------------------------------------
// LIF scan + maxpool2. Chunked in time with warm-up from mem=0.
// start = max(0, t0 - WARM): chunks whose warm-up reaches t=0 are EXACT.
// R12 evidence: seams contribute zero flips at this WARM (rel_err invariant
// under chunking changes), so this scheme is numerically safe.
// Exact reference rounding order:  mem = ((0.9*mem) + v) - reset
// ---------------------------------------------------------------------------
#define SCAN_CHUNK 2048
#define SCAN_WARM  3072

template <int C, int T, bool FINAL>
__global__ __launch_bounds__(128) void scan_kernel(float* __restrict__ dout,
                                                   const float* __restrict__ gamma,
                                                   const float* __restrict__ beta) {
    constexpr int NCH = T / SCAN_CHUNK;
    const int gid  = blockIdx.x * blockDim.x + threadIdx.x;
    const int lane = gid / NCH;          // (b*C + c)
    const int q    = gid % NCH;
    if (lane >= 32 * C) return;
    const int c = lane % C;

    const float mean = g_mean[c];
    const float inv  = g_inv[c];
    const float ga   = __ldg(gamma + c);
    const float be   = __ldg(beta + c);

    const float* row = g_bufA + (size_t)lane * T;
    float* dst = FINAL ? dout : g_bufS;
    float* outp = dst + (size_t)lane * (T / 2) + (q * SCAN_CHUNK) / 2;

    const int t0    = q * SCAN_CHUNK;
    int start = t0 - SCAN_WARM;
    if (start < 0) start = 0;
    const int ngw   = (t0 - start) / 32;        // warm-up groups
    const int ngo   = SCAN_CHUNK / 32;          // output groups
    const int total = ngw + ngo;

    const float4* rp = reinterpret_cast<const float4*>(row + start);
    float4 cur[8], nxt[8];
#pragma unroll
    for (int i = 0; i < 8; i++) cur[i] = rp[i];
    rp += 8;

    float mem = 0.0f;

    for (int gi = 0; gi < total; gi++) {
        const bool last = (gi == total - 1);
        if (!last) {
#pragma unroll
            for (int i = 0; i < 8; i++) nxt[i] = rp[i];
            rp += 8;
        }
        float po[16];
#pragma unroll
        for (int i = 0; i < 8; i++) {
            const float4 v4 = cur[i];
            float vx[4];
            vx[0] = v4.x; vx[1] = v4.y; vx[2] = v4.z; vx[3] = v4.w;
            float mm[4];
#pragma unroll
            for (int s = 0; s < 4; s++) {
                // BN: ((x - mean) * inv) * gamma + beta, op-by-op rounding
                const float v = __fadd_rn(__fmul_rn(__fmul_rn(__fsub_rn(vx[s], mean), inv), ga), be);
                // LIF: reset from previous mem, then mem = (0.9*mem + v) - reset
                const float r  = (mem > 1.0f) ? 1.0f : 0.0f;
                const float m2 = __fadd_rn(__fmul_rn(0.9f, mem), v);
                mem = __fsub_rn(m2, r);
                mm[s] = mem;
            }
            // spikes = (mem > 1), pooled pairs -> OR == (max(mem) > 1)
            po[2 * i + 0] = (fmaxf(mm[0], mm[1]) > 1.0f) ? 1.0f : 0.0f;
            po[2 * i + 1] = (fmaxf(mm[2], mm[3]) > 1.0f) ? 1.0f : 0.0f;
        }
        if (gi >= ngw) {
#pragma unroll
            for (int i2 = 0; i2 < 4; i2++)
                reinterpret_cast<float4*>(outp)[i2] =
                    make_float4(po[4 * i2], po[4 * i2 + 1], po[4 * i2 + 2], po[4 * i2 + 3]);
            outp += 16;
        }
        if (!last) {
#pragma unroll
            for (int i = 0; i < 8; i++) cur[i] = nxt[i];
        }
    }
}

// ---------------------------------------------------------------------------
extern "C" void kernel_launch(void* const* d_in, const int* in_sizes, int n_in,
                              void* d_out, int out_size) {
    const float* x   = (const float*)d_in[0];
    const float* w1  = (const float*)d_in[1];
    const float* b1  = (const float*)d_in[2];
    const float* g1  = (const float*)d_in[3];
    const float* be1 = (const float*)d_in[4];
    const float* w2  = (const float*)d_in[5];
    const float* b2  = (const float*)d_in[6];
    const float* g2  = (const float*)d_in[7];
    const float* be2 = (const float*)d_in[8];
    const float* w3  = (const float*)d_in[9];
    const float* b3  = (const float*)d_in[10];
    const float* g3  = (const float*)d_in[11];
    const float* be3 = (const float*)d_in[12];
    float* out = (float*)d_out;
    (void)in_sizes; (void)n_in; (void)out_size;

    // ---- Layer 1 ----
    conv1_kernel<<<dim3(16, 16, 32), 128>>>(x, w1, b1);
    stats_kernel<16, 16384><<<dim3(16, 32), 256>>>();
    stats_fin_kernel<16, 16384><<<1, 16>>>();
    // lanes=512, NCH=8 -> 4096 threads
    scan_kernel<16, 16384, false><<<32, 128>>>(nullptr, g1, be1);

    // ---- Layer 2 ----
    convN_kernel<16, 32, 5, 8192, 2><<<dim3(8, 8, 32), 128>>>(w2, b2);
    stats_kernel<32, 8192><<<dim3(32, 32), 256>>>();
    stats_fin_kernel<32, 8192><<<1, 32>>>();
    // lanes=1024, NCH=4 -> 4096 threads
    scan_kernel<32, 8192, false><<<32, 128>>>(nullptr, g2, be2);

    // ---- Layer 3 ----
    convN_kernel<32, 64, 3, 4096, 1><<<dim3(4, 16, 32), 128>>>(w3, b3);
    stats_kernel<64, 4096><<<dim3(64, 32), 256>>>();
    stats_fin_kernel<64, 4096><<<1, 64>>>();
    // lanes=2048, NCH=2 -> 4096 threads (all chunks exact: warm reaches t=0)
    scan_kernel<64, 4096, true><<<32, 128>>>(out, g3, be3);
}

// round 16
// speedup vs baseline: 1.3794x; 1.3794x over previous
#include <cuda_runtime.h>

// ============================================================================
// SpikingCNN: conv1d -> BN(train) -> LIF -> maxpool2, three blocks.
// B=32. L1: 2->16 K5 s4 p2 T65536->16384->8192
//       L2: 16->32 K5 s1 p2 T8192->8192->4096
//       L3: 32->64 K3 s1 p1 T4096->4096->2048
// R15: PASSED rel_err=0.0 at 647us. ncu: scans are 3x136us with grid=32,
// occ 6.2% -> 1 warp/SMSP, chain stalls fully exposed (~48 cyc/step).
// R15 change: CHUNK 2048->256, WARM 3072->768 => 32768 threads/scan,
// 256 blocks, ~1.7 warps/SMSP chip-wide. W=512 proven zero-seam-flip
// (R1 vs R12 identical flip sets); 768 = 1.5x margin.
// ============================================================================

// Scratch (device globals; no allocation allowed)
__device__ float  g_bufA[8388608];   // conv outputs (all three layers are 8.39M)
__device__ float  g_bufS[4194304];   // spike outputs of L1 then L2
__device__ double g_psum[64 * 32];
__device__ double g_psq [64 * 32];
__device__ float  g_mean[64];
__device__ float  g_inv [64];

static __device__ __forceinline__ float4 ld4g(const float* __restrict__ p, int idx, int n) {
    // idx is always a multiple of 4 and n a multiple of 4 -> whole float4 in or out
    if (idx >= 0 && idx < n) return *reinterpret_cast<const float4*>(p + idx);
    return make_float4(0.f, 0.f, 0.f, 0.f);
}

// ---------------------------------------------------------------------------
// conv1: x(32,2,65536) -> g_bufA(32,16,16384), K=5, stride=4, pad=2
// ---------------------------------------------------------------------------
__global__ __launch_bounds__(128) void conv1_kernel(const float* __restrict__ x,
                                                    const float* __restrict__ w,
                                                    const float* __restrict__ bias) {
    const int g  = blockIdx.x * blockDim.x + threadIdx.x;  // 0..2047 (16384/8)
    const int co = blockIdx.y;                             // 0..15
    const int b  = blockIdx.z;                             // 0..31

    float wv[2][5];
#pragma unroll
    for (int ci = 0; ci < 2; ci++)
#pragma unroll
        for (int k = 0; k < 5; k++)
            wv[ci][k] = __ldg(w + (co * 2 + ci) * 5 + k);

    float acc[8];
    const float bb = __ldg(bias + co);
#pragma unroll
    for (int j = 0; j < 8; j++) acc[j] = bb;

    const int base = 32 * g - 4;
#pragma unroll
    for (int ci = 0; ci < 2; ci++) {
        const float* row = x + (b * 2 + ci) * 65536;
        float win[36];
#pragma unroll
        for (int q = 0; q < 9; q++) {
            float4 v = ld4g(row, base + 4 * q, 65536);
            win[4 * q + 0] = v.x; win[4 * q + 1] = v.y;
            win[4 * q + 2] = v.z; win[4 * q + 3] = v.w;
        }
#pragma unroll
        for (int k = 0; k < 5; k++)
#pragma unroll
            for (int j = 0; j < 8; j++)
                acc[j] = fmaf(wv[ci][k], win[4 * j + k + 2], acc[j]);  // idx = 4t+k-2
    }

    float* out = g_bufA + (b * 16 + co) * 16384 + 8 * g;
    *reinterpret_cast<float4*>(out)     = make_float4(acc[0], acc[1], acc[2], acc[3]);
    *reinterpret_cast<float4*>(out + 4) = make_float4(acc[4], acc[5], acc[6], acc[7]);
}

// ---------------------------------------------------------------------------
// convN (layers 2,3): reads spikes from g_bufS, writes g_bufA.
// Thread computes 4 couts x 8 t (register blocked), weights staged in smem.
// ---------------------------------------------------------------------------
template <int CIN, int COUT, int K, int T, int PAD>
__global__ __launch_bounds__(128) void convN_kernel(const float* __restrict__ w,
                                                    const float* __restrict__ bias) {
    __shared__ __align__(16) float ws[CIN * K * 4];
    const int tid = threadIdx.x;
    const int co4 = blockIdx.y;  // group of 4 output channels
    const int b   = blockIdx.z;

    for (int i = tid; i < CIN * K * 4; i += blockDim.x) {
        const int ci = i / (K * 4);
        const int r  = i % (K * 4);
        const int k  = r / 4;
        const int c  = r % 4;
        ws[i] = w[((co4 * 4 + c) * CIN + ci) * K + k];
    }
    __syncthreads();

    const int g    = blockIdx.x * blockDim.x + tid;  // 0..T/8-1
    const int base = 8 * g - 4;

    float acc[4][8];
#pragma unroll
    for (int c = 0; c < 4; c++) {
        const float bb = __ldg(bias + co4 * 4 + c);
#pragma unroll
        for (int j = 0; j < 8; j++) acc[c][j] = bb;
    }

    for (int ci = 0; ci < CIN; ci++) {
        const float* row = g_bufS + (b * CIN + ci) * T;
        float win[16];
#pragma unroll
        for (int q = 0; q < 4; q++) {
            float4 v = ld4g(row, base + 4 * q, T);
            win[4 * q + 0] = v.x; win[4 * q + 1] = v.y;
            win[4 * q + 2] = v.z; win[4 * q + 3] = v.w;
        }
#pragma unroll
        for (int k = 0; k < K; k++) {
            const float4 wv = *reinterpret_cast<const float4*>(&ws[(ci * K + k) * 4]);
#pragma unroll
            for (int j = 0; j < 8; j++) {
                const float xv = win[j + k + (4 - PAD)];  // idx = t + k - PAD
                acc[0][j] = fmaf(wv.x, xv, acc[0][j]);
                acc[1][j] = fmaf(wv.y, xv, acc[1][j]);
                acc[2][j] = fmaf(wv.z, xv, acc[2][j]);
                acc[3][j] = fmaf(wv.w, xv, acc[3][j]);
            }
        }
    }

#pragma unroll
    for (int c = 0; c < 4; c++) {
        float* out = g_bufA + (b * COUT + co4 * 4 + c) * T + 8 * g;
        *reinterpret_cast<float4*>(out)     = make_float4(acc[c][0], acc[c][1], acc[c][2], acc[c][3]);
        *reinterpret_cast<float4*>(out + 4) = make_float4(acc[c][4], acc[c][5], acc[c][6], acc[c][7]);
    }
}

// ---------------------------------------------------------------------------
// BN stats: single pass, fp64 sum + sum-of-squares. Block = one (c, b) row.
// ---------------------------------------------------------------------------
template <int C, int T>
__global__ void stats_kernel() {
    const int c = blockIdx.x, b = blockIdx.y;
    const float* row = g_bufA + (b * C + c) * T;
    double s = 0.0, q = 0.0;
    for (int t = threadIdx.x; t < T; t += 256) {
        const double v = (double)row[t];
        s += v;
        q += v * v;
    }
    __shared__ double shs[256];
    __shared__ double shq[256];
    shs[threadIdx.x] = s;
    shq[threadIdx.x] = q;
    __syncthreads();
    for (int o = 128; o > 0; o >>= 1) {
        if (threadIdx.x < o) {
            shs[threadIdx.x] += shs[threadIdx.x + o];
            shq[threadIdx.x] += shq[threadIdx.x + o];
        }
        __syncthreads();
    }
    if (threadIdx.x == 0) {
        g_psum[c * 32 + b] = shs[0];
        g_psq [c * 32 + b] = shq[0];
    }
}

template <int C, int T>
__global__ void stats_fin_kernel() {
    const int c = threadIdx.x;
    if (c >= C) return;
    double s = 0.0, q = 0.0;
    for (int i = 0; i < 32; i++) { s += g_psum[c * 32 + i]; q += g_psq[c * 32 + i]; }
    const double N    = (double)(32 * (long long)T);
    const double mean = s / N;
    const double var  = q / N - mean * mean;
    g_mean[c] = (float)mean;
    // Match reference: var in fp32, eps added in fp32, libdevice rsqrtf
    // (this exact formulation produced rel_err = 0.0 in R15).
    const float var_f = (float)var;
    g_inv[c]  = rsqrtf(var_f + 1e-5f);
}

// ---------------------------------------------------------------------------
// LIF scan + maxpool2. Chunked in time with warm-up from mem=0.
// start = max(0, t0 - WARM): chunks whose warm-up reaches t=0 are EXACT.
// W=512 empirically contributed ZERO seam flips (R1 vs R12 identical flip
// sets over ~22k seams); WARM=768 adds 1.5x margin.
// Exact reference rounding order:  mem = ((0.9*mem) + v) - reset
// ---------------------------------------------------------------------------
#define SCAN_CHUNK 256
#define SCAN_WARM  768

template <int C, int T, bool FINAL>
__global__ __launch_bounds__(128) void scan_kernel(float* __restrict__ dout,
                                                   const float* __restrict__ gamma,
                                                   const float* __restrict__ beta) {
    constexpr int NCH = T / SCAN_CHUNK;
    const int gid  = blockIdx.x * blockDim.x + threadIdx.x;
    const int lane = gid / NCH;          // (b*C + c)
    const int q    = gid % NCH;
    if (lane >= 32 * C) return;
    const int c = lane % C;

    const float mean = g_mean[c];
    const float inv  = g_inv[c];
    const float ga   = __ldg(gamma + c);
    const float be   = __ldg(beta + c);

    const float* row = g_bufA + (size_t)lane * T;
    float* dst = FINAL ? dout : g_bufS;
    float* outp = dst + (size_t)lane * (T / 2) + (q * SCAN_CHUNK) / 2;

    const int t0    = q * SCAN_CHUNK;
    int start = t0 - SCAN_WARM;
    if (start < 0) start = 0;
    const int ngw   = (t0 - start) / 32;        // warm-up groups
    const int ngo   = SCAN_CHUNK / 32;          // output groups
    const int total = ngw + ngo;

    const float4* rp = reinterpret_cast<const float4*>(row + start);
    float4 cur[8], nxt[8];
#pragma unroll
    for (int i = 0; i < 8; i++) cur[i] = rp[i];
    rp += 8;

    float mem = 0.0f;

    for (int gi = 0; gi < total; gi++) {
        const bool last = (gi == total - 1);
        if (!last) {
#pragma unroll
            for (int i = 0; i < 8; i++) nxt[i] = rp[i];
            rp += 8;
        }
        float po[16];
#pragma unroll
        for (int i = 0; i < 8; i++) {
            const float4 v4 = cur[i];
            float vx[4];
            vx[0] = v4.x; vx[1] = v4.y; vx[2] = v4.z; vx[3] = v4.w;
            float mm[4];
#pragma unroll
            for (int s = 0; s < 4; s++) {
                // BN: ((x - mean) * inv) * gamma + beta, op-by-op rounding
                const float v = __fadd_rn(__fmul_rn(__fmul_rn(__fsub_rn(vx[s], mean), inv), ga), be);
                // LIF: reset from previous mem, then mem = (0.9*mem + v) - reset
                const float r  = (mem > 1.0f) ? 1.0f : 0.0f;
                const float m2 = __fadd_rn(__fmul_rn(0.9f, mem), v);
                mem = __fsub_rn(m2, r);
                mm[s] = mem;
            }
            // spikes = (mem > 1), pooled pairs -> OR == (max(mem) > 1)
            po[2 * i + 0] = (fmaxf(mm[0], mm[1]) > 1.0f) ? 1.0f : 0.0f;
            po[2 * i + 1] = (fmaxf(mm[2], mm[3]) > 1.0f) ? 1.0f : 0.0f;
        }
        if (gi >= ngw) {
#pragma unroll
            for (int i2 = 0; i2 < 4; i2++)
                reinterpret_cast<float4*>(outp)[i2] =
                    make_float4(po[4 * i2], po[4 * i2 + 1], po[4 * i2 + 2], po[4 * i2 + 3]);
            outp += 16;
        }
        if (!last) {
#pragma unroll
            for (int i = 0; i < 8; i++) cur[i] = nxt[i];
        }
    }
}

// ---------------------------------------------------------------------------
extern "C" void kernel_launch(void* const* d_in, const int* in_sizes, int n_in,
                              void* d_out, int out_size) {
    const float* x   = (const float*)d_in[0];
    const float* w1  = (const float*)d_in[1];
    const float* b1  = (const float*)d_in[2];
    const float* g1  = (const float*)d_in[3];
    const float* be1 = (const float*)d_in[4];
    const float* w2  = (const float*)d_in[5];
    const float* b2  = (const float*)d_in[6];
    const float* g2  = (const float*)d_in[7];
    const float* be2 = (const float*)d_in[8];
    const float* w3  = (const float*)d_in[9];
    const float* b3  = (const float*)d_in[10];
    const float* g3  = (const float*)d_in[11];
    const float* be3 = (const float*)d_in[12];
    float* out = (float*)d_out;
    (void)in_sizes; (void)n_in; (void)out_size;

    // ---- Layer 1 ----
    conv1_kernel<<<dim3(16, 16, 32), 128>>>(x, w1, b1);
    stats_kernel<16, 16384><<<dim3(16, 32), 256>>>();
    stats_fin_kernel<16, 16384><<<1, 16>>>();
    // lanes=512, NCH=64 -> 32768 threads, 256 blocks
    scan_kernel<16, 16384, false><<<256, 128>>>(nullptr, g1, be1);

    // ---- Layer 2 ----
    convN_kernel<16, 32, 5, 8192, 2><<<dim3(8, 8, 32), 128>>>(w2, b2);
    stats_kernel<32, 8192><<<dim3(32, 32), 256>>>();
    stats_fin_kernel<32, 8192><<<1, 32>>>();
    // lanes=1024, NCH=32 -> 32768 threads, 256 blocks
    scan_kernel<32, 8192, false><<<256, 128>>>(nullptr, g2, be2);

    // ---- Layer 3 ----
    convN_kernel<32, 64, 3, 4096, 1><<<dim3(4, 16, 32), 128>>>(w3, b3);
    stats_kernel<64, 4096><<<dim3(64, 32), 256>>>();
    stats_fin_kernel<64, 4096><<<1, 64>>>();
    // lanes=2048, NCH=16 -> 32768 threads, 256 blocks
    scan_kernel<64, 4096, true><<<256, 128>>>(out, g3, be3);
}

// round 17
// speedup vs baseline: 1.4603x; 1.0586x over previous
#include <cuda_runtime.h>

// ============================================================================
// SpikingCNN: conv1d -> BN(train) -> LIF -> maxpool2, three blocks.
// B=32. L1: 2->16 K5 s4 p2 T65536->16384->8192
//       L2: 16->32 K5 s1 p2 T8192->8192->4096
//       L3: 32->64 K3 s1 p1 T4096->4096->2048
// R15: PASS rel_err=0.0 (rsqrtf match). R16: 469us; scans 43us each,
// L1=67.9% => uncoalesced per-chain loads (32 lines/LDG) are the wall.
// R17: smem-staged coalesced scan loads (wave model, double buffer),
// WARM 768->512 (W=512 proven zero-seam-flip: R1 vs R12 identical flips).
// ============================================================================

// Scratch (device globals; no allocation allowed)
__device__ float  g_bufA[8388608];   // conv outputs
__device__ float  g_bufS[4194304];   // spike outputs of L1 then L2
__device__ double g_psum[64 * 32];
__device__ double g_psq [64 * 32];
__device__ float  g_mean[64];
__device__ float  g_inv [64];

static __device__ __forceinline__ float4 ld4g(const float* __restrict__ p, int idx, int n) {
    if (idx >= 0 && idx < n) return *reinterpret_cast<const float4*>(p + idx);
    return make_float4(0.f, 0.f, 0.f, 0.f);
}

// ---------------------------------------------------------------------------
// conv1: x(32,2,65536) -> g_bufA(32,16,16384), K=5, stride=4, pad=2
// ---------------------------------------------------------------------------
__global__ __launch_bounds__(128) void conv1_kernel(const float* __restrict__ x,
                                                    const float* __restrict__ w,
                                                    const float* __restrict__ bias) {
    const int g  = blockIdx.x * blockDim.x + threadIdx.x;
    const int co = blockIdx.y;
    const int b  = blockIdx.z;

    float wv[2][5];
#pragma unroll
    for (int ci = 0; ci < 2; ci++)
#pragma unroll
        for (int k = 0; k < 5; k++)
            wv[ci][k] = __ldg(w + (co * 2 + ci) * 5 + k);

    float acc[8];
    const float bb = __ldg(bias + co);
#pragma unroll
    for (int j = 0; j < 8; j++) acc[j] = bb;

    const int base = 32 * g - 4;
#pragma unroll
    for (int ci = 0; ci < 2; ci++) {
        const float* row = x + (b * 2 + ci) * 65536;
        float win[36];
#pragma unroll
        for (int q = 0; q < 9; q++) {
            float4 v = ld4g(row, base + 4 * q, 65536);
            win[4 * q + 0] = v.x; win[4 * q + 1] = v.y;
            win[4 * q + 2] = v.z; win[4 * q + 3] = v.w;
        }
#pragma unroll
        for (int k = 0; k < 5; k++)
#pragma unroll
            for (int j = 0; j < 8; j++)
                acc[j] = fmaf(wv[ci][k], win[4 * j + k + 2], acc[j]);
    }

    float* out = g_bufA + (b * 16 + co) * 16384 + 8 * g;
    *reinterpret_cast<float4*>(out)     = make_float4(acc[0], acc[1], acc[2], acc[3]);
    *reinterpret_cast<float4*>(out + 4) = make_float4(acc[4], acc[5], acc[6], acc[7]);
}

// ---------------------------------------------------------------------------
// convN (layers 2,3): reads spikes from g_bufS, writes g_bufA.
// ---------------------------------------------------------------------------
template <int CIN, int COUT, int K, int T, int PAD>
__global__ __launch_bounds__(128) void convN_kernel(const float* __restrict__ w,
                                                    const float* __restrict__ bias) {
    __shared__ __align__(16) float ws[CIN * K * 4];
    const int tid = threadIdx.x;
    const int co4 = blockIdx.y;
    const int b   = blockIdx.z;

    for (int i = tid; i < CIN * K * 4; i += blockDim.x) {
        const int ci = i / (K * 4);
        const int r  = i % (K * 4);
        const int k  = r / 4;
        const int c  = r % 4;
        ws[i] = w[((co4 * 4 + c) * CIN + ci) * K + k];
    }
    __syncthreads();

    const int g    = blockIdx.x * blockDim.x + tid;
    const int base = 8 * g - 4;

    float acc[4][8];
#pragma unroll
    for (int c = 0; c < 4; c++) {
        const float bb = __ldg(bias + co4 * 4 + c);
#pragma unroll
        for (int j = 0; j < 8; j++) acc[c][j] = bb;
    }

    for (int ci = 0; ci < CIN; ci++) {
        const float* row = g_bufS + (b * CIN + ci) * T;
        float win[16];
#pragma unroll
        for (int q = 0; q < 4; q++) {
            float4 v = ld4g(row, base + 4 * q, T);
            win[4 * q + 0] = v.x; win[4 * q + 1] = v.y;
            win[4 * q + 2] = v.z; win[4 * q + 3] = v.w;
        }
#pragma unroll
        for (int k = 0; k < K; k++) {
            const float4 wv = *reinterpret_cast<const float4*>(&ws[(ci * K + k) * 4]);
#pragma unroll
            for (int j = 0; j < 8; j++) {
                const float xv = win[j + k + (4 - PAD)];
                acc[0][j] = fmaf(wv.x, xv, acc[0][j]);
                acc[1][j] = fmaf(wv.y, xv, acc[1][j]);
                acc[2][j] = fmaf(wv.z, xv, acc[2][j]);
                acc[3][j] = fmaf(wv.w, xv, acc[3][j]);
            }
        }
    }

#pragma unroll
    for (int c = 0; c < 4; c++) {
        float* out = g_bufA + (b * COUT + co4 * 4 + c) * T + 8 * g;
        *reinterpret_cast<float4*>(out)     = make_float4(acc[c][0], acc[c][1], acc[c][2], acc[c][3]);
        *reinterpret_cast<float4*>(out + 4) = make_float4(acc[c][4], acc[c][5], acc[c][6], acc[c][7]);
    }
}

// ---------------------------------------------------------------------------
// BN stats: single pass, fp64 sum + sum-of-squares. Block = one (c, b) row.
// ---------------------------------------------------------------------------
template <int C, int T>
__global__ void stats_kernel() {
    const int c = blockIdx.x, b = blockIdx.y;
    const float* row = g_bufA + (b * C + c) * T;
    double s = 0.0, q = 0.0;
    for (int t = threadIdx.x; t < T; t += 256) {
        const double v = (double)row[t];
        s += v;
        q += v * v;
    }
    __shared__ double shs[256];
    __shared__ double shq[256];
    shs[threadIdx.x] = s;
    shq[threadIdx.x] = q;
    __syncthreads();
    for (int o = 128; o > 0; o >>= 1) {
        if (threadIdx.x < o) {
            shs[threadIdx.x] += shs[threadIdx.x + o];
            shq[threadIdx.x] += shq[threadIdx.x + o];
        }
        __syncthreads();
    }
    if (threadIdx.x == 0) {
        g_psum[c * 32 + b] = shs[0];
        g_psq [c * 32 + b] = shq[0];
    }
}

template <int C, int T>
__global__ void stats_fin_kernel() {
    const int c = threadIdx.x;
    if (c >= C) return;
    double s = 0.0, q = 0.0;
    for (int i = 0; i < 32; i++) { s += g_psum[c * 32 + i]; q += g_psq[c * 32 + i]; }
    const double N    = (double)(32 * (long long)T);
    const double mean = s / N;
    const double var  = q / N - mean * mean;
    g_mean[c] = (float)mean;
    // fp32 var + fp32 eps + libdevice rsqrtf: produced rel_err = 0.0 in R15.
    const float var_f = (float)var;
    g_inv[c]  = rsqrtf(var_f + 1e-5f);
}

// ---------------------------------------------------------------------------
// LIF scan + maxpool2, wave-structured with coalesced smem staging.
// Block = 128 consecutive chains (chain = lane*NCH + q). Per 32-step wave the
// block loads all needed 128B segments coalesced into padded smem (stride 33,
// conflict-free), double-buffered with register prefetch. Chains with
// start=0 (q*CHUNK <= WARM) are EXACT (true initial state); others warm up
// 512 steps (proven zero-flip: R1 W=512 vs R12 W=3072 identical flip sets).
// Exact reference rounding order:  mem = ((0.9*mem) + v) - reset
// ---------------------------------------------------------------------------
#define SCAN_CHUNK 256
#define SCAN_WARM  512
#define SCAN_GW    (SCAN_WARM / 32)            // 16 warm waves
#define SCAN_GO    (SCAN_CHUNK / 32)           // 8 output waves
#define SCAN_WAVES (SCAN_GW + SCAN_GO)         // 24

template <int C, int T, bool FINAL>
__global__ __launch_bounds__(128) void scan_kernel(float* __restrict__ dout,
                                                   const float* __restrict__ gamma,
                                                   const float* __restrict__ beta) {
    constexpr int NCH = T / SCAN_CHUNK;        // chunks per lane (64/32/16)
    const int tid    = threadIdx.x;
    const int chain0 = blockIdx.x * 128;
    const int chain  = chain0 + tid;
    const int lane   = chain / NCH;
    const int q      = chain % NCH;
    const int c      = lane % C;

    // my schedule: active waves [first, SCAN_WAVES); output waves are the
    // last SCAN_GO for everyone.
    const int t0 = q * SCAN_CHUNK;
    int start = t0 - SCAN_WARM; if (start < 0) start = 0;
    const int first = SCAN_WAVES - ((t0 - start) / 32 + SCAN_GO);

    __shared__ float sm[2][128 * 33];

    const float mean = g_mean[c];
    const float inv  = g_inv[c];
    const float ga   = __ldg(gamma + c);
    const float be   = __ldg(beta + c);

    float* dst  = FINAL ? dout : g_bufS;
    float* outp = dst + (size_t)lane * (T / 2) + q * (SCAN_CHUNK / 2);

    // loader mapping: 8 rounds; round r stages segment j = r*16 + tid/8,
    // this thread provides floats [k4, k4+4) of that 32-float segment.
    const int seg_sub = tid >> 3;              // 0..15
    const int k4      = (tid & 7) * 4;         // 0..28

    float4 stage[8];

    // ---- prologue: stage wave 0 ----
#pragma unroll
    for (int r = 0; r < 8; r++) {
        const int j   = r * 16 + seg_sub;
        const int chj = chain0 + j;
        const int lj  = chj / NCH, qj = chj % NCH;
        const int t0j = qj * SCAN_CHUNK;
        int sj = t0j - SCAN_WARM; if (sj < 0) sj = 0;
        const int fj = SCAN_WAVES - ((t0j - sj) / 32 + SCAN_GO);
        stage[r] = make_float4(0.f, 0.f, 0.f, 0.f);
        if (0 >= fj) {
            const int t = sj + (0 - fj) * 32 + k4;
            stage[r] = *reinterpret_cast<const float4*>(g_bufA + (size_t)lj * T + t);
        }
    }
#pragma unroll
    for (int r = 0; r < 8; r++) {
        float* s = &sm[0][(r * 16 + seg_sub) * 33 + k4];
        s[0] = stage[r].x; s[1] = stage[r].y; s[2] = stage[r].z; s[3] = stage[r].w;
    }
    __syncthreads();

    float mem = 0.0f;

    for (int gi = 0; gi < SCAN_WAVES; gi++) {
        const int p = gi & 1;

        // prefetch wave gi+1 into registers (overlaps with compute below)
        if (gi + 1 < SCAN_WAVES) {
#pragma unroll
            for (int r = 0; r < 8; r++) {
                const int j   = r * 16 + seg_sub;
                const int chj = chain0 + j;
                const int lj  = chj / NCH, qj = chj % NCH;
                const int t0j = qj * SCAN_CHUNK;
                int sj = t0j - SCAN_WARM; if (sj < 0) sj = 0;
                const int fj = SCAN_WAVES - ((t0j - sj) / 32 + SCAN_GO);
                if (gi + 1 >= fj) {
                    const int t = sj + (gi + 1 - fj) * 32 + k4;
                    stage[r] = *reinterpret_cast<const float4*>(g_bufA + (size_t)lj * T + t);
                }
            }
        }

        // compute 32 steps from sm[p]
        if (gi >= first) {
            const float* myrow = &sm[p][tid * 33];
            float po[16];
#pragma unroll
            for (int s2 = 0; s2 < 16; s2++) {
                float m0, m1;
                {
                    const float xv = myrow[2 * s2];
                    const float v  = __fadd_rn(__fmul_rn(__fmul_rn(__fsub_rn(xv, mean), inv), ga), be);
                    const float rr = (mem > 1.0f) ? 1.0f : 0.0f;
                    mem = __fsub_rn(__fadd_rn(__fmul_rn(0.9f, mem), v), rr);
                    m0 = mem;
                }
                {
                    const float xv = myrow[2 * s2 + 1];
                    const float v  = __fadd_rn(__fmul_rn(__fmul_rn(__fsub_rn(xv, mean), inv), ga), be);
                    const float rr = (mem > 1.0f) ? 1.0f : 0.0f;
                    mem = __fsub_rn(__fadd_rn(__fmul_rn(0.9f, mem), v), rr);
                    m1 = mem;
                }
                po[s2] = (fmaxf(m0, m1) > 1.0f) ? 1.0f : 0.0f;
            }
            if (gi >= SCAN_GW) {
                float4* o = reinterpret_cast<float4*>(outp + (gi - SCAN_GW) * 16);
                o[0] = make_float4(po[0],  po[1],  po[2],  po[3]);
                o[1] = make_float4(po[4],  po[5],  po[6],  po[7]);
                o[2] = make_float4(po[8],  po[9],  po[10], po[11]);
                o[3] = make_float4(po[12], po[13], po[14], po[15]);
            }
        }

        // commit prefetched wave gi+1 into the other buffer
        if (gi + 1 < SCAN_WAVES) {
#pragma unroll
            for (int r = 0; r < 8; r++) {
                float* s = &sm[1 - p][(r * 16 + seg_sub) * 33 + k4];
                s[0] = stage[r].x; s[1] = stage[r].y; s[2] = stage[r].z; s[3] = stage[r].w;
            }
        }
        __syncthreads();
    }
}

// ---------------------------------------------------------------------------
extern "C" void kernel_launch(void* const* d_in, const int* in_sizes, int n_in,
                              void* d_out, int out_size) {
    const float* x   = (const float*)d_in[0];
    const float* w1  = (const float*)d_in[1];
    const float* b1  = (const float*)d_in[2];
    const float* g1  = (const float*)d_in[3];
    const float* be1 = (const float*)d_in[4];
    const float* w2  = (const float*)d_in[5];
    const float* b2  = (const float*)d_in[6];
    const float* g2  = (const float*)d_in[7];
    const float* be2 = (const float*)d_in[8];
    const float* w3  = (const float*)d_in[9];
    const float* b3  = (const float*)d_in[10];
    const float* g3  = (const float*)d_in[11];
    const float* be3 = (const float*)d_in[12];
    float* out = (float*)d_out;
    (void)in_sizes; (void)n_in; (void)out_size;

    // ---- Layer 1 ----
    conv1_kernel<<<dim3(16, 16, 32), 128>>>(x, w1, b1);
    stats_kernel<16, 16384><<<dim3(16, 32), 256>>>();
    stats_fin_kernel<16, 16384><<<1, 16>>>();
    // chains = 512 lanes * 64 = 32768 -> 256 blocks
    scan_kernel<16, 16384, false><<<256, 128>>>(nullptr, g1, be1);

    // ---- Layer 2 ----
    convN_kernel<16, 32, 5, 8192, 2><<<dim3(8, 8, 32), 128>>>(w2, b2);
    stats_kernel<32, 8192><<<dim3(32, 32), 256>>>();
    stats_fin_kernel<32, 8192><<<1, 32>>>();
    // chains = 1024 * 32 = 32768 -> 256 blocks
    scan_kernel<32, 8192, false><<<256, 128>>>(nullptr, g2, be2);

    // ---- Layer 3 ----
    convN_kernel<32, 64, 3, 4096, 1><<<dim3(4, 16, 32), 128>>>(w3, b3);
    stats_kernel<64, 4096><<<dim3(64, 32), 256>>>();
    stats_fin_kernel<64, 4096><<<1, 64>>>();
    // chains = 2048 * 16 = 32768 -> 256 blocks
    scan_kernel<64, 4096, true><<<256, 128>>>(out, g3, be3);
}